// round 16
// baseline (speedup 1.0000x reference)
#include <cuda_runtime.h>
#include <cooperative_groups.h>
#include <math.h>
#include <stdint.h>

namespace cg = cooperative_groups;

#define N_NODES 384
#define H 256
#define Z 128
#define ED 128
#define AH 64
#define H4 1024
#define NE (N_NODES * N_NODES)

// ------------------------- scratch (device globals) -------------------------
__device__ float g_nodes[N_NODES * H];       // [384,256]
__device__ float g_Amat[N_NODES * H4];       // nodes@W1a + eg_b1
__device__ float g_Bmat[N_NODES * H4];       // nodes@W1b
__device__ float g_M[H4 * ED];               // egW2@[a0W1e|a1W1e]  [1024,128]
__device__ float g_cb0[AH];                  // egb2@a0W1e + a0b1
__device__ float g_cb1[AH];                  // egb2@a1W1e + a1b1
__device__ float g_Xc0[N_NODES * AH];        // nodes@a0W1x + cb0
__device__ float g_hid1[(size_t)NE * AH];    // att1 half of hidden, [s][d][64]
__device__ float g_Att0T[NE];                // att0 matrix, [d][s]
__device__ float g_agg0[N_NODES * H];
__device__ float g_x1[N_NODES * H];
__device__ float g_v[H];                     // sum_s w[s] * x1[s]

// --------------------------- packed f32x2 helpers ---------------------------
__device__ __forceinline__ void ffma2(unsigned long long& acc,
                                      unsigned long long a,
                                      unsigned long long b) {
  asm("fma.rn.f32x2 %0, %1, %2, %0;" : "+l"(acc) : "l"(a), "l"(b));
}
__device__ __forceinline__ float2 up2(unsigned long long v) {
  float2 r;
  r.x = __uint_as_float((unsigned)(v & 0xffffffffull));
  r.y = __uint_as_float((unsigned)(v >> 32));
  return r;
}
__device__ __forceinline__ unsigned long long dup2(float f) {
  unsigned long long r;
  asm("mov.b64 %0, {%1, %1};" : "=l"(r) : "f"(f));
  return r;
}
__device__ __forceinline__ float fast_sigmoid(float x) {
  return __fdividef(1.f, 1.f + __expf(-x));
}
__device__ __forceinline__ float fast_tanh(float x) {
  float xc = fminf(fmaxf(x, -15.f), 15.f);
  float e2 = __expf(2.f * xc);
  return __fdividef(e2 - 1.f, e2 + 1.f);
}

// ------------------------------- GRU kernel ---------------------------------
// (proven R12/R13 form — 8-CTA cluster, reg-resident Whh, cluster.sync,
//  plain per-thread f32 DSMEM broadcast; do NOT re-add store pairing)
#define GRU_CTAS 8
#define GRU_HPC 32
#define GRU_ROWS 96

__global__ void __cluster_dims__(GRU_CTAS, 1, 1) __launch_bounds__(384)
gru_kernel(const float* __restrict__ z, const float* __restrict__ Wih,
           const float* __restrict__ Whh, const float* __restrict__ bih,
           const float* __restrict__ bhh) {
  __shared__ float hbuf[2][H];
  __shared__ float part[4 * GRU_ROWS];
  __shared__ float gi[GRU_ROWS];
  __shared__ float bh[GRU_ROWS];
  cg::cluster_group cluster = cg::this_cluster();
  const int c = cluster.block_rank();
  const int tid = threadIdx.x;
  const int w = tid >> 5, l = tid & 31;
  const int gate = w % 3, kq = w / 3;
  const int r = gate * 32 + l;
  const int grow = gate * H + c * GRU_HPC + l;

  unsigned long long wr[32];
  {
    const float* wsrc = &Whh[(size_t)grow * H + kq * 64];
#pragma unroll
    for (int j = 0; j < 16; j++) {
      ulonglong2 t = *(const ulonglong2*)&wsrc[j * 4];
      wr[2 * j] = t.x;
      wr[2 * j + 1] = t.y;
    }
  }
  for (int rr = tid; rr < GRU_ROWS; rr += 384) {
    int g2 = rr >> 5, i2 = rr & 31;
    int gr = g2 * H + c * GRU_HPC + i2;
    float s = bih[gr];
    for (int k = 0; k < Z; k++) s += Wih[gr * Z + k] * z[k];
    gi[rr] = s;
    bh[rr] = bhh[gr];
  }
  for (int k = tid; k < 2 * H; k += 384) hbuf[0][k] = 0.f;
  __syncthreads();
  cluster.sync();

  for (int step = 0; step < N_NODES; step++) {
    const int cur = step & 1, nxt = cur ^ 1;
    {
      const float* hsrc = &hbuf[cur][kq * 64];
      unsigned long long a0 = 0, a1 = 0, a2 = 0, a3 = 0;
#pragma unroll
      for (int j = 0; j < 16; j += 2) {
        ulonglong2 hv0 = *(const ulonglong2*)&hsrc[j * 4];
        ulonglong2 hv1 = *(const ulonglong2*)&hsrc[j * 4 + 4];
        ffma2(a0, wr[2 * j], hv0.x);
        ffma2(a1, wr[2 * j + 1], hv0.y);
        ffma2(a2, wr[2 * j + 2], hv1.x);
        ffma2(a3, wr[2 * j + 3], hv1.y);
      }
      float2 s0 = up2(a0), s1 = up2(a1), s2 = up2(a2), s3 = up2(a3);
      part[kq * GRU_ROWS + r] =
          ((s0.x + s0.y) + (s1.x + s1.y)) + ((s2.x + s2.y) + (s3.x + s3.y));
    }
    __syncthreads();
    if (tid < GRU_HPC) {
      const int i = tid;
      float ghr = part[i] + part[96 + i] + part[192 + i] + part[288 + i] + bh[i];
      float ghz = part[32 + i] + part[96 + 32 + i] + part[192 + 32 + i] +
                  part[288 + 32 + i] + bh[32 + i];
      float ghn = part[64 + i] + part[96 + 64 + i] + part[192 + 64 + i] +
                  part[288 + 64 + i] + bh[64 + i];
      float rg = fast_sigmoid(gi[i] + ghr);
      float ug = fast_sigmoid(gi[32 + i] + ghz);
      float ng = fast_tanh(gi[64 + i] + rg * ghn);
      float h2 = (1.f - ug) * ng + ug * hbuf[cur][c * GRU_HPC + i];
      g_nodes[step * H + c * GRU_HPC + i] = h2;
#pragma unroll
      for (int rk = 0; rk < GRU_CTAS; rk++) {
        float* remote = (float*)cluster.map_shared_rank(hbuf, rk);
        remote[nxt * H + c * GRU_HPC + i] = h2;
      }
    }
    cluster.sync();
  }
}

// ------------------ setup kernel: M GEMM + cb vectors + zero v --------------
__global__ void setup_kernel(const float* __restrict__ egW2,
                             const float* __restrict__ a0W1,
                             const float* __restrict__ a1W1,
                             const float* __restrict__ egb2,
                             const float* __restrict__ a0b1,
                             const float* __restrict__ a1b1) {
  if (blockIdx.z == 2) {
    if (blockIdx.y != 0) return;
    const int t = threadIdx.x;  // 256
    g_v[t] = 0.f;
    if (t < AH) {
      float s = a0b1[t];
#pragma unroll 8
      for (int k = 0; k < ED; k++) s += egb2[k] * a0W1[k * AH + t];
      g_cb0[t] = s;
    } else if (t < 2 * AH) {
      const int i = t - AH;
      float s = a1b1[i];
#pragma unroll 8
      for (int k = 0; k < ED; k++) s += egb2[k] * a1W1[k * AH + i];
      g_cb1[i] = s;
    }
    return;
  }
  const float* B = blockIdx.z ? a1W1 : a0W1;
  float* C = blockIdx.z ? (g_M + AH) : g_M;
  __shared__ float As[16][68];
  __shared__ float Bs[16][68];
  const int tx = threadIdx.x % 16, ty = threadIdx.x / 16;
  const int m0 = blockIdx.y * 64;
  float acc[4][4] = {};
  for (int k0 = 0; k0 < ED; k0 += 16) {
    for (int idx = threadIdx.x; idx < 64 * 16; idx += 256) {
      int m = idx / 16, k = idx % 16;
      As[k][m] = egW2[(size_t)(m0 + m) * ED + k0 + k];
    }
    for (int idx = threadIdx.x; idx < 16 * 64; idx += 256) {
      int k = idx / 64, n = idx % 64;
      Bs[k][n] = B[(size_t)(k0 + k) * AH + n];
    }
    __syncthreads();
#pragma unroll
    for (int k = 0; k < 16; k++) {
      float a[4], b[4];
#pragma unroll
      for (int i = 0; i < 4; i++) a[i] = As[k][ty * 4 + i];
#pragma unroll
      for (int j = 0; j < 4; j++) b[j] = Bs[k][tx * 4 + j];
#pragma unroll
      for (int i = 0; i < 4; i++)
#pragma unroll
        for (int j = 0; j < 4; j++) acc[i][j] += a[i] * b[j];
    }
    __syncthreads();
  }
#pragma unroll
  for (int i = 0; i < 4; i++)
#pragma unroll
    for (int j = 0; j < 4; j++)
      C[(size_t)(m0 + ty * 4 + i) * ED + tx * 4 + j] = acc[i][j];
}

// -------------- A/B/Xc0 GEMM: z selects output (64x64 tiles) ----------------
__global__ void abxc_kernel(const float* __restrict__ nodes,
                            const float* __restrict__ egW1,
                            const float* __restrict__ egb1,
                            const float* __restrict__ a0W1x) {
  const float* B;
  const float* bias;
  float* C;
  int ldb, ldc;
  if (blockIdx.z == 0) {
    B = egW1; bias = egb1; C = g_Amat; ldb = H4; ldc = H4;
  } else if (blockIdx.z == 1) {
    B = egW1 + (size_t)H * H4; bias = nullptr; C = g_Bmat; ldb = H4; ldc = H4;
  } else {
    if (blockIdx.x != 0) return;
    B = a0W1x; bias = g_cb0; C = g_Xc0; ldb = AH; ldc = AH;
  }
  __shared__ float As[16][68];
  __shared__ float Bs[16][68];
  const int tx = threadIdx.x % 16, ty = threadIdx.x / 16;
  const int m0 = blockIdx.y * 64, n0 = blockIdx.x * 64;
  float acc[4][4] = {};
  for (int k0 = 0; k0 < H; k0 += 16) {
    for (int idx = threadIdx.x; idx < 64 * 16; idx += 256) {
      int m = idx / 16, k = idx % 16;
      As[k][m] = nodes[(size_t)(m0 + m) * H + k0 + k];
    }
    for (int idx = threadIdx.x; idx < 16 * 64; idx += 256) {
      int k = idx / 64, n = idx % 64;
      Bs[k][n] = B[(size_t)(k0 + k) * ldb + n0 + n];
    }
    __syncthreads();
#pragma unroll
    for (int k = 0; k < 16; k++) {
      float a[4], b[4];
#pragma unroll
      for (int i = 0; i < 4; i++) a[i] = As[k][ty * 4 + i];
#pragma unroll
      for (int j = 0; j < 4; j++) b[j] = Bs[k][tx * 4 + j];
#pragma unroll
      for (int i = 0; i < 4; i++)
#pragma unroll
        for (int j = 0; j < 4; j++) acc[i][j] += a[i] * b[j];
    }
    __syncthreads();
  }
#pragma unroll
  for (int i = 0; i < 4; i++)
#pragma unroll
    for (int j = 0; j < 4; j++) {
      float v = acc[i][j] + (bias ? bias[n0 + tx * 4 + j] : 0.f);
      C[(size_t)(m0 + ty * 4 + i) * ldc + n0 + tx * 4 + j] = v;
    }
}

// ------------------- gemm32: 32x64 tiles (latency-hiding) -------------------
template <bool RELU>
__global__ void gemm32_kernel(int M, int N, int K, const float* __restrict__ A,
                              int lda, const float* __restrict__ B, int ldb,
                              const float* __restrict__ bias,
                              float* __restrict__ C, int ldc) {
  __shared__ float As[16][36];
  __shared__ float Bs[16][68];
  const int tx = threadIdx.x % 16, ty = threadIdx.x / 16;
  const int m0 = blockIdx.y * 32, n0 = blockIdx.x * 64;
  float acc[2][4] = {};
  for (int k0 = 0; k0 < K; k0 += 16) {
    for (int idx = threadIdx.x; idx < 32 * 16; idx += 256) {
      int m = idx / 16, k = idx % 16;
      As[k][m] = A[(size_t)(m0 + m) * lda + k0 + k];
    }
    for (int idx = threadIdx.x; idx < 16 * 64; idx += 256) {
      int k = idx / 64, n = idx % 64;
      Bs[k][n] = B[(size_t)(k0 + k) * ldb + n0 + n];
    }
    __syncthreads();
#pragma unroll
    for (int k = 0; k < 16; k++) {
      float a[2], b[4];
#pragma unroll
      for (int i = 0; i < 2; i++) a[i] = As[k][ty * 2 + i];
#pragma unroll
      for (int j = 0; j < 4; j++) b[j] = Bs[k][tx * 4 + j];
#pragma unroll
      for (int i = 0; i < 2; i++)
#pragma unroll
        for (int j = 0; j < 4; j++) acc[i][j] += a[i] * b[j];
    }
    __syncthreads();
  }
#pragma unroll
  for (int i = 0; i < 2; i++)
#pragma unroll
    for (int j = 0; j < 4; j++) {
      float v = acc[i][j] + (bias ? bias[n0 + tx * 4 + j] : 0.f);
      if (RELU) v = fmaxf(v, 0.f);
      C[(size_t)(m0 + ty * 2 + i) * ldc + n0 + tx * 4 + j] = v;
    }
}

// ------------------- f32x2 edge GEMM + fused attention-0 --------------------
// (frozen — double-buffered, 8d x 8ch, reg-packed M)
#define ETS_LD 192

__global__ void __launch_bounds__(256, 2) edge_kernel(
    const float* __restrict__ a0W2, const float* __restrict__ a0b2) {
  __shared__ float asv[H4];
  __shared__ float Ts[2][16][ETS_LD];
  __shared__ float Msm[2][16][ED];
  __shared__ float xcw[AH], w2s[AH];
  float(*patt)[9] = (float(*)[9]) & Ts[0][0][0];

  const int s = blockIdx.y;
  const int d0 = blockIdx.x * 128;
  const int tid = threadIdx.x;

  for (int i = tid; i < H4; i += 256) asv[i] = g_Amat[(size_t)s * H4 + i];
  if (tid < AH) {
    xcw[tid] = g_Xc0[s * AH + tid];
    w2s[tid] = a0W2[tid];
  }

  const int sdd = tid >> 1;
  const int skh = (tid & 1) * 8;
  const int scol = sdd + ((sdd >> 3) << 2);
  const float* bsrc = &g_Bmat[(size_t)(d0 + sdd) * H4];

  const int dt = (tid & 15) * 8;
  const int acol = dt + ((dt >> 3) << 2);
  const int ct = (tid >> 4) * 8;
  unsigned long long acc[4][8] = {};

  {
    float4 b0 = *(const float4*)&bsrc[skh];
    float4 b1 = *(const float4*)&bsrc[skh + 4];
    const float4* msrc = (const float4*)&g_M[0];
    float4 mr0 = msrc[tid];
    float4 mr1 = msrc[256 + tid];
    const float* av = &asv[skh];
    Ts[0][skh + 0][scol] = fmaxf(av[0] + b0.x, 0.f);
    Ts[0][skh + 1][scol] = fmaxf(av[1] + b0.y, 0.f);
    Ts[0][skh + 2][scol] = fmaxf(av[2] + b0.z, 0.f);
    Ts[0][skh + 3][scol] = fmaxf(av[3] + b0.w, 0.f);
    Ts[0][skh + 4][scol] = fmaxf(av[4] + b1.x, 0.f);
    Ts[0][skh + 5][scol] = fmaxf(av[5] + b1.y, 0.f);
    Ts[0][skh + 6][scol] = fmaxf(av[6] + b1.z, 0.f);
    Ts[0][skh + 7][scol] = fmaxf(av[7] + b1.w, 0.f);
    ((float4*)&Msm[0][0][0])[tid] = mr0;
    ((float4*)&Msm[0][0][0])[256 + tid] = mr1;
  }
  __syncthreads();

  for (int tile = 0; tile < 64; tile++) {
    const int cur = tile & 1;
    float4 b0, b1, mr0, mr1;
    if (tile < 63) {
      const int kn = (tile + 1) * 16;
      b0 = *(const float4*)&bsrc[kn + skh];
      b1 = *(const float4*)&bsrc[kn + skh + 4];
      const float4* msrc = (const float4*)&g_M[(size_t)kn * ED];
      mr0 = msrc[tid];
      mr1 = msrc[256 + tid];
    }
#pragma unroll
    for (int k = 0; k < 16; k++) {
      ulonglong2 aA = *(const ulonglong2*)&Ts[cur][k][acol];
      ulonglong2 aB = *(const ulonglong2*)&Ts[cur][k][acol + 4];
      float4 m0 = *(const float4*)&Msm[cur][k][ct];
      float4 m1 = *(const float4*)&Msm[cur][k][ct + 4];
      const float mv[8] = {m0.x, m0.y, m0.z, m0.w, m1.x, m1.y, m1.z, m1.w};
#pragma unroll
      for (int c = 0; c < 8; c++) {
        const unsigned long long mm = dup2(mv[c]);
        ffma2(acc[0][c], aA.x, mm);
        ffma2(acc[1][c], aA.y, mm);
        ffma2(acc[2][c], aB.x, mm);
        ffma2(acc[3][c], aB.y, mm);
      }
    }
    if (tile < 63) {
      const int nb = cur ^ 1;
      const float* av = &asv[(tile + 1) * 16 + skh];
      Ts[nb][skh + 0][scol] = fmaxf(av[0] + b0.x, 0.f);
      Ts[nb][skh + 1][scol] = fmaxf(av[1] + b0.y, 0.f);
      Ts[nb][skh + 2][scol] = fmaxf(av[2] + b0.z, 0.f);
      Ts[nb][skh + 3][scol] = fmaxf(av[3] + b0.w, 0.f);
      Ts[nb][skh + 4][scol] = fmaxf(av[4] + b1.x, 0.f);
      Ts[nb][skh + 5][scol] = fmaxf(av[5] + b1.y, 0.f);
      Ts[nb][skh + 6][scol] = fmaxf(av[6] + b1.z, 0.f);
      Ts[nb][skh + 7][scol] = fmaxf(av[7] + b1.w, 0.f);
      ((float4*)&Msm[nb][0][0])[tid] = mr0;
      ((float4*)&Msm[nb][0][0])[256 + tid] = mr1;
    }
    __syncthreads();
  }

  const int ctg = tid >> 4;
  if (ct < AH) {
#pragma unroll
    for (int p = 0; p < 4; p++) {
      float se = 0.f, so = 0.f;
#pragma unroll
      for (int c = 0; c < 8; c++) {
        float2 v = up2(acc[p][c]);
        se += fmaxf(v.x + xcw[ct + c], 0.f) * w2s[ct + c];
        so += fmaxf(v.y + xcw[ct + c], 0.f) * w2s[ct + c];
      }
      patt[dt + 2 * p][ctg] = se;
      patt[dt + 2 * p + 1][ctg] = so;
    }
  } else {
    const int chb = ct - AH;
#pragma unroll
    for (int p = 0; p < 4; p++) {
      float2 v0 = up2(acc[p][0]), v1 = up2(acc[p][1]);
      float2 v2 = up2(acc[p][2]), v3 = up2(acc[p][3]);
      float2 v4 = up2(acc[p][4]), v5 = up2(acc[p][5]);
      float2 v6 = up2(acc[p][6]), v7 = up2(acc[p][7]);
      const size_t base = ((size_t)s * N_NODES + d0 + dt + 2 * p) * AH + chb;
      *(float4*)&g_hid1[base] = make_float4(v0.x, v1.x, v2.x, v3.x);
      *(float4*)&g_hid1[base + 4] = make_float4(v4.x, v5.x, v6.x, v7.x);
      *(float4*)&g_hid1[base + AH] = make_float4(v0.y, v1.y, v2.y, v3.y);
      *(float4*)&g_hid1[base + AH + 4] = make_float4(v4.y, v5.y, v6.y, v7.y);
    }
  }
  __syncthreads();
  if (tid < 128) {
    float v = 0.f;
#pragma unroll
    for (int g = 0; g < 8; g++) v += patt[tid][g];
    float att = (d0 + tid == s) ? 0.f : fast_sigmoid(v + a0b2[0]);
    g_Att0T[(size_t)(d0 + tid) * N_NODES + s] = att;
  }
}

// ---------- attention layer 1 row-sums + fused v accumulation ---------------
__global__ void att1w_kernel(const float* __restrict__ a1W1,
                             const float* __restrict__ a1W2,
                             const float* __restrict__ a1b2) {
  const int s = blockIdx.x;
  const int warp = threadIdx.x >> 5, lane = threadIdx.x & 31;
  __shared__ float pxc[AH][5];
  __shared__ float xc[AH], w2[AH];
  __shared__ float wsum[8];
  __shared__ float wtot;
  {
    const int i = threadIdx.x >> 2, q = threadIdx.x & 3;
    const float* xs = &g_x1[s * H + q * 64];
    const float* wcol = &a1W1[(size_t)(ED + q * 64) * AH + i];
    float acc = 0.f;
#pragma unroll 8
    for (int k = 0; k < 64; k++) acc += xs[k] * wcol[k * AH];
    pxc[i][q] = acc;
  }
  __syncthreads();
  if (threadIdx.x < AH) {
    xc[threadIdx.x] = pxc[threadIdx.x][0] + pxc[threadIdx.x][1] +
                      pxc[threadIdx.x][2] + pxc[threadIdx.x][3] +
                      g_cb1[threadIdx.x];
    w2[threadIdx.x] = a1W2[threadIdx.x];
  }
  __syncthreads();
  const float b2 = a1b2[0];
  float accv = 0.f;
  for (int d = warp; d < N_NODES; d += 8) {
    float2 h2 = *(const float2*)&g_hid1[(((size_t)s) * N_NODES + d) * AH + lane * 2];
    float v = fmaxf(h2.x + xc[lane * 2], 0.f) * w2[lane * 2] +
              fmaxf(h2.y + xc[lane * 2 + 1], 0.f) * w2[lane * 2 + 1];
    for (int o = 16; o > 0; o >>= 1) v += __shfl_down_sync(0xffffffffu, v, o);
    if (lane == 0 && d != s) accv += fast_sigmoid(v + b2);
  }
  if (lane == 0) wsum[warp] = accv;
  __syncthreads();
  if (threadIdx.x == 0) {
    float t = 0.f;
    for (int i = 0; i < 8; i++) t += wsum[i];
    wtot = t;
  }
  __syncthreads();
  // v += w[s] * x1[s]  (spread-address float atomics; 256 lanes in parallel)
  atomicAdd(&g_v[threadIdx.x], wtot * g_x1[s * H + threadIdx.x]);
}

// --------------------------- final: out = v @ c1W ---------------------------
__global__ void final2_kernel(const float* __restrict__ c1W,
                              const float* __restrict__ c1b,
                              float* __restrict__ out) {
  __shared__ float v[H];
  const int tid = threadIdx.x;  // 256
  v[tid] = g_v[tid];
  __syncthreads();
  float o = (float)N_NODES * c1b[tid];
#pragma unroll 8
  for (int h = 0; h < H; h++) o += v[h] * c1W[h * H + tid];
  out[tid] = o;
}

// ------------------------------- launcher -----------------------------------
static float* sym_addr(const void* symbol) {
  void* p = nullptr;
  cudaGetSymbolAddress(&p, symbol);
  return (float*)p;
}

extern "C" void kernel_launch(void* const* d_in, const int* in_sizes, int n_in,
                              void* d_out, int out_size) {
  const float* z = (const float*)d_in[0];
  const float* Wih = (const float*)d_in[1];
  const float* Whh = (const float*)d_in[2];
  const float* bih = (const float*)d_in[3];
  const float* bhh = (const float*)d_in[4];
  const float* egW1 = (const float*)d_in[5];
  const float* egb1 = (const float*)d_in[6];
  const float* egW2 = (const float*)d_in[7];
  const float* egb2 = (const float*)d_in[8];
  const float* a0W1 = (const float*)d_in[9];
  const float* a0b1 = (const float*)d_in[10];
  const float* a0W2 = (const float*)d_in[11];
  const float* a0b2 = (const float*)d_in[12];
  const float* a1W1 = (const float*)d_in[13];
  const float* a1b1 = (const float*)d_in[14];
  const float* a1W2 = (const float*)d_in[15];
  const float* a1b2 = (const float*)d_in[16];
  const float* c0W = (const float*)d_in[17];
  const float* c0b = (const float*)d_in[18];
  const float* c1W = (const float*)d_in[19];
  const float* c1b = (const float*)d_in[20];
  float* out = (float*)d_out;

  float* nodes = sym_addr(g_nodes);
  float* Att0T = sym_addr(g_Att0T);
  float* agg0 = sym_addr(g_agg0);
  float* x1 = sym_addr(g_x1);

  // 0: setup — M halves (z=0,1) + cb0/cb1 + zero g_v (z=2)
  setup_kernel<<<dim3(1, H4 / 64, 3), 256>>>(egW2, a0W1, a1W1, egb2, a0b1,
                                             a1b1);

  // 1: GRU -> nodes
  gru_kernel<<<GRU_CTAS, 384>>>(z, Wih, Whh, bih, bhh);

  // 2: A/B/Xc0 (z=0: Amat, z=1: Bmat, z=2: Xc0)
  abxc_kernel<<<dim3(H4 / 64, N_NODES / 64, 3), 256>>>(
      nodes, egW1, egb1, a0W1 + (size_t)ED * AH);

  // 3 (PROFILED): edge GEMM + fused att0
  edge_kernel<<<dim3(N_NODES / 128, N_NODES), 256>>>(a0W2, a0b2);

  // 4: agg0 = Att0T @ nodes
  gemm32_kernel<false><<<dim3(H / 64, N_NODES / 32), 256>>>(
      N_NODES, H, N_NODES, Att0T, N_NODES, nodes, H, nullptr, agg0, H);

  // 5: x1 = relu(agg0 @ c0W + c0b)
  gemm32_kernel<true><<<dim3(H / 64, N_NODES / 32), 256>>>(
      N_NODES, H, H, agg0, H, c0W, H, c0b, x1, H);

  // 6: w[s] + atomic v accumulation
  att1w_kernel<<<N_NODES, 256>>>(a1W1, a1W2, a1b2);

  // 7: out = v @ c1W + 384*c1b
  final2_kernel<<<1, H>>>(c1W, c1b, out);
}

// round 17
// speedup vs baseline: 1.0756x; 1.0756x over previous
#include <cuda_runtime.h>
#include <cooperative_groups.h>
#include <math.h>
#include <stdint.h>

namespace cg = cooperative_groups;

#define N_NODES 384
#define H 256
#define Z 128
#define ED 128
#define AH 64
#define H4 1024
#define NE (N_NODES * N_NODES)

// ------------------------- scratch (device globals) -------------------------
__device__ float g_nodes[N_NODES * H];       // [384,256]
__device__ float g_Amat[N_NODES * H4];       // nodes@W1a + eg_b1
__device__ float g_Bmat[N_NODES * H4];       // nodes@W1b
__device__ float g_M[H4 * ED];               // egW2@[a0W1e|a1W1e]  [1024,128]
__device__ float g_cb0[AH];                  // egb2@a0W1e + a0b1
__device__ float g_cb1[AH];                  // egb2@a1W1e + a1b1
__device__ float g_Xc0[N_NODES * AH];        // nodes@a0W1x + cb0
__device__ float g_hid1[(size_t)NE * AH];    // att1 half of hidden, [s][d][64]
__device__ float g_Att0T[NE];                // att0 matrix, [d][s]
__device__ float g_x1[N_NODES * H];
__device__ float g_w[N_NODES];

// --------------------------- packed f32x2 helpers ---------------------------
__device__ __forceinline__ void ffma2(unsigned long long& acc,
                                      unsigned long long a,
                                      unsigned long long b) {
  asm("fma.rn.f32x2 %0, %1, %2, %0;" : "+l"(acc) : "l"(a), "l"(b));
}
__device__ __forceinline__ float2 up2(unsigned long long v) {
  float2 r;
  r.x = __uint_as_float((unsigned)(v & 0xffffffffull));
  r.y = __uint_as_float((unsigned)(v >> 32));
  return r;
}
__device__ __forceinline__ unsigned long long dup2(float f) {
  unsigned long long r;
  asm("mov.b64 %0, {%1, %1};" : "=l"(r) : "f"(f));
  return r;
}
__device__ __forceinline__ float fast_sigmoid(float x) {
  return __fdividef(1.f, 1.f + __expf(-x));
}
__device__ __forceinline__ float fast_tanh(float x) {
  float xc = fminf(fmaxf(x, -15.f), 15.f);
  float e2 = __expf(2.f * xc);
  return __fdividef(e2 - 1.f, e2 + 1.f);
}

// ------------------------------- GRU kernel ---------------------------------
// (frozen R12/R13 — 8-CTA cluster, reg-resident Whh, cluster.sync, fast-math)
#define GRU_CTAS 8
#define GRU_HPC 32
#define GRU_ROWS 96

__global__ void __cluster_dims__(GRU_CTAS, 1, 1) __launch_bounds__(384)
gru_kernel(const float* __restrict__ z, const float* __restrict__ Wih,
           const float* __restrict__ Whh, const float* __restrict__ bih,
           const float* __restrict__ bhh) {
  __shared__ float hbuf[2][H];
  __shared__ float part[4 * GRU_ROWS];
  __shared__ float gi[GRU_ROWS];
  __shared__ float bh[GRU_ROWS];
  cg::cluster_group cluster = cg::this_cluster();
  const int c = cluster.block_rank();
  const int tid = threadIdx.x;
  const int w = tid >> 5, l = tid & 31;
  const int gate = w % 3, kq = w / 3;
  const int r = gate * 32 + l;
  const int grow = gate * H + c * GRU_HPC + l;

  unsigned long long wr[32];
  {
    const float* wsrc = &Whh[(size_t)grow * H + kq * 64];
#pragma unroll
    for (int j = 0; j < 16; j++) {
      ulonglong2 t = *(const ulonglong2*)&wsrc[j * 4];
      wr[2 * j] = t.x;
      wr[2 * j + 1] = t.y;
    }
  }
  for (int rr = tid; rr < GRU_ROWS; rr += 384) {
    int g2 = rr >> 5, i2 = rr & 31;
    int gr = g2 * H + c * GRU_HPC + i2;
    float s = bih[gr];
    for (int k = 0; k < Z; k++) s += Wih[gr * Z + k] * z[k];
    gi[rr] = s;
    bh[rr] = bhh[gr];
  }
  for (int k = tid; k < 2 * H; k += 384) hbuf[0][k] = 0.f;
  __syncthreads();
  cluster.sync();

  for (int step = 0; step < N_NODES; step++) {
    const int cur = step & 1, nxt = cur ^ 1;
    {
      const float* hsrc = &hbuf[cur][kq * 64];
      unsigned long long a0 = 0, a1 = 0, a2 = 0, a3 = 0;
#pragma unroll
      for (int j = 0; j < 16; j += 2) {
        ulonglong2 hv0 = *(const ulonglong2*)&hsrc[j * 4];
        ulonglong2 hv1 = *(const ulonglong2*)&hsrc[j * 4 + 4];
        ffma2(a0, wr[2 * j], hv0.x);
        ffma2(a1, wr[2 * j + 1], hv0.y);
        ffma2(a2, wr[2 * j + 2], hv1.x);
        ffma2(a3, wr[2 * j + 3], hv1.y);
      }
      float2 s0 = up2(a0), s1 = up2(a1), s2 = up2(a2), s3 = up2(a3);
      part[kq * GRU_ROWS + r] =
          ((s0.x + s0.y) + (s1.x + s1.y)) + ((s2.x + s2.y) + (s3.x + s3.y));
    }
    __syncthreads();
    if (tid < GRU_HPC) {
      const int i = tid;
      float ghr = part[i] + part[96 + i] + part[192 + i] + part[288 + i] + bh[i];
      float ghz = part[32 + i] + part[96 + 32 + i] + part[192 + 32 + i] +
                  part[288 + 32 + i] + bh[32 + i];
      float ghn = part[64 + i] + part[96 + 64 + i] + part[192 + 64 + i] +
                  part[288 + 64 + i] + bh[64 + i];
      float rg = fast_sigmoid(gi[i] + ghr);
      float ug = fast_sigmoid(gi[32 + i] + ghz);
      float ng = fast_tanh(gi[64 + i] + rg * ghn);
      float h2 = (1.f - ug) * ng + ug * hbuf[cur][c * GRU_HPC + i];
      g_nodes[step * H + c * GRU_HPC + i] = h2;
#pragma unroll
      for (int rk = 0; rk < GRU_CTAS; rk++) {
        float* remote = (float*)cluster.map_shared_rank(hbuf, rk);
        remote[nxt * H + c * GRU_HPC + i] = h2;
      }
    }
    cluster.sync();
  }
}

// ------------------ setup kernel: M GEMM + cb vectors -----------------------
__global__ void setup_kernel(const float* __restrict__ egW2,
                             const float* __restrict__ a0W1,
                             const float* __restrict__ a1W1,
                             const float* __restrict__ egb2,
                             const float* __restrict__ a0b1,
                             const float* __restrict__ a1b1) {
  if (blockIdx.z == 2) {
    if (blockIdx.y != 0) return;
    const int t = threadIdx.x;  // 256
    if (t < AH) {
      float s = a0b1[t];
#pragma unroll 8
      for (int k = 0; k < ED; k++) s += egb2[k] * a0W1[k * AH + t];
      g_cb0[t] = s;
    } else if (t < 2 * AH) {
      const int i = t - AH;
      float s = a1b1[i];
#pragma unroll 8
      for (int k = 0; k < ED; k++) s += egb2[k] * a1W1[k * AH + i];
      g_cb1[i] = s;
    }
    return;
  }
  const float* B = blockIdx.z ? a1W1 : a0W1;
  float* C = blockIdx.z ? (g_M + AH) : g_M;
  __shared__ float As[16][68];
  __shared__ float Bs[16][68];
  const int tx = threadIdx.x % 16, ty = threadIdx.x / 16;
  const int m0 = blockIdx.y * 64;
  float acc[4][4] = {};
  for (int k0 = 0; k0 < ED; k0 += 16) {
    for (int idx = threadIdx.x; idx < 64 * 16; idx += 256) {
      int m = idx / 16, k = idx % 16;
      As[k][m] = egW2[(size_t)(m0 + m) * ED + k0 + k];
    }
    for (int idx = threadIdx.x; idx < 16 * 64; idx += 256) {
      int k = idx / 64, n = idx % 64;
      Bs[k][n] = B[(size_t)(k0 + k) * AH + n];
    }
    __syncthreads();
#pragma unroll
    for (int k = 0; k < 16; k++) {
      float a[4], b[4];
#pragma unroll
      for (int i = 0; i < 4; i++) a[i] = As[k][ty * 4 + i];
#pragma unroll
      for (int j = 0; j < 4; j++) b[j] = Bs[k][tx * 4 + j];
#pragma unroll
      for (int i = 0; i < 4; i++)
#pragma unroll
        for (int j = 0; j < 4; j++) acc[i][j] += a[i] * b[j];
    }
    __syncthreads();
  }
#pragma unroll
  for (int i = 0; i < 4; i++)
#pragma unroll
    for (int j = 0; j < 4; j++)
      C[(size_t)(m0 + ty * 4 + i) * ED + tx * 4 + j] = acc[i][j];
}

// -------------- A/B/Xc0 GEMM: z selects output (64x64 tiles) ----------------
__global__ void abxc_kernel(const float* __restrict__ nodes,
                            const float* __restrict__ egW1,
                            const float* __restrict__ egb1,
                            const float* __restrict__ a0W1x) {
  const float* B;
  const float* bias;
  float* C;
  int ldb, ldc;
  if (blockIdx.z == 0) {
    B = egW1; bias = egb1; C = g_Amat; ldb = H4; ldc = H4;
  } else if (blockIdx.z == 1) {
    B = egW1 + (size_t)H * H4; bias = nullptr; C = g_Bmat; ldb = H4; ldc = H4;
  } else {
    if (blockIdx.x != 0) return;
    B = a0W1x; bias = g_cb0; C = g_Xc0; ldb = AH; ldc = AH;
  }
  __shared__ float As[16][68];
  __shared__ float Bs[16][68];
  const int tx = threadIdx.x % 16, ty = threadIdx.x / 16;
  const int m0 = blockIdx.y * 64, n0 = blockIdx.x * 64;
  float acc[4][4] = {};
  for (int k0 = 0; k0 < H; k0 += 16) {
    for (int idx = threadIdx.x; idx < 64 * 16; idx += 256) {
      int m = idx / 16, k = idx % 16;
      As[k][m] = nodes[(size_t)(m0 + m) * H + k0 + k];
    }
    for (int idx = threadIdx.x; idx < 16 * 64; idx += 256) {
      int k = idx / 64, n = idx % 64;
      Bs[k][n] = B[(size_t)(k0 + k) * ldb + n0 + n];
    }
    __syncthreads();
#pragma unroll
    for (int k = 0; k < 16; k++) {
      float a[4], b[4];
#pragma unroll
      for (int i = 0; i < 4; i++) a[i] = As[k][ty * 4 + i];
#pragma unroll
      for (int j = 0; j < 4; j++) b[j] = Bs[k][tx * 4 + j];
#pragma unroll
      for (int i = 0; i < 4; i++)
#pragma unroll
        for (int j = 0; j < 4; j++) acc[i][j] += a[i] * b[j];
    }
    __syncthreads();
  }
#pragma unroll
  for (int i = 0; i < 4; i++)
#pragma unroll
    for (int j = 0; j < 4; j++) {
      float v = acc[i][j] + (bias ? bias[n0 + tx * 4 + j] : 0.f);
      C[(size_t)(m0 + ty * 4 + i) * ldc + n0 + tx * 4 + j] = v;
    }
}

// ---------- fused conv: x1 = relu((Att0T @ nodes) @ c0W + c0b) --------------
// CTA owns 16 output rows; agg strip parked in smem (never hits global).
// Thread tile: 4 rows (ty=tid>>6) x 4 cols (tx=tid&63). 24 CTAs x 256 thr.
__global__ void __launch_bounds__(256) fusedconv_kernel(
    const float* __restrict__ c0W, const float* __restrict__ c0b) {
  __shared__ float agg[16][264];
  __shared__ float Bs[16][264];
  __shared__ float As[16][20];
  const int tid = threadIdx.x;
  const int tx = tid & 63, ty = tid >> 6;
  const int m0 = blockIdx.y * 16;

  float acc[4][4] = {};
  // phase 1: agg = Att0T[m0..m0+16) @ nodes   (K = 384)
  for (int k0 = 0; k0 < N_NODES; k0 += 16) {
    {
      int r = tid >> 4, k = tid & 15;
      As[k][r] = g_Att0T[(size_t)(m0 + r) * N_NODES + k0 + k];
    }
#pragma unroll
    for (int j = 0; j < 4; j++) {
      int idx = j * 256 + tid;           // 1024 float4
      int k = idx >> 6, nq = idx & 63;
      *(float4*)&Bs[k][nq * 4] = *(const float4*)&g_nodes[(k0 + k) * H + nq * 4];
    }
    __syncthreads();
#pragma unroll
    for (int k = 0; k < 16; k++) {
      float a[4];
      float4 b = *(const float4*)&Bs[k][tx * 4];
#pragma unroll
      for (int i = 0; i < 4; i++) a[i] = As[k][ty * 4 + i];
#pragma unroll
      for (int i = 0; i < 4; i++) {
        acc[i][0] += a[i] * b.x;
        acc[i][1] += a[i] * b.y;
        acc[i][2] += a[i] * b.z;
        acc[i][3] += a[i] * b.w;
      }
    }
    __syncthreads();
  }
  // park agg strip in smem
#pragma unroll
  for (int i = 0; i < 4; i++)
    *(float4*)&agg[ty * 4 + i][tx * 4] =
        make_float4(acc[i][0], acc[i][1], acc[i][2], acc[i][3]);
  __syncthreads();

  // phase 2: x1 = relu(agg @ c0W + c0b)   (K = 256)
  float acc2[4][4] = {};
  for (int k0 = 0; k0 < H; k0 += 16) {
#pragma unroll
    for (int j = 0; j < 4; j++) {
      int idx = j * 256 + tid;
      int k = idx >> 6, nq = idx & 63;
      *(float4*)&Bs[k][nq * 4] = *(const float4*)&c0W[(k0 + k) * H + nq * 4];
    }
    __syncthreads();
#pragma unroll
    for (int k = 0; k < 16; k++) {
      float a[4];
      float4 b = *(const float4*)&Bs[k][tx * 4];
#pragma unroll
      for (int i = 0; i < 4; i++) a[i] = agg[ty * 4 + i][k0 + k];
#pragma unroll
      for (int i = 0; i < 4; i++) {
        acc2[i][0] += a[i] * b.x;
        acc2[i][1] += a[i] * b.y;
        acc2[i][2] += a[i] * b.z;
        acc2[i][3] += a[i] * b.w;
      }
    }
    __syncthreads();
  }
#pragma unroll
  for (int i = 0; i < 4; i++) {
    float4 o;
    o.x = fmaxf(acc2[i][0] + c0b[tx * 4 + 0], 0.f);
    o.y = fmaxf(acc2[i][1] + c0b[tx * 4 + 1], 0.f);
    o.z = fmaxf(acc2[i][2] + c0b[tx * 4 + 2], 0.f);
    o.w = fmaxf(acc2[i][3] + c0b[tx * 4 + 3], 0.f);
    *(float4*)&g_x1[(size_t)(m0 + ty * 4 + i) * H + tx * 4] = o;
  }
}

// ------------------- f32x2 edge GEMM + fused attention-0 --------------------
// (frozen — double-buffered, 8d x 8ch, reg-packed M)
#define ETS_LD 192

__global__ void __launch_bounds__(256, 2) edge_kernel(
    const float* __restrict__ a0W2, const float* __restrict__ a0b2) {
  __shared__ float asv[H4];
  __shared__ float Ts[2][16][ETS_LD];
  __shared__ float Msm[2][16][ED];
  __shared__ float xcw[AH], w2s[AH];
  float(*patt)[9] = (float(*)[9]) & Ts[0][0][0];

  const int s = blockIdx.y;
  const int d0 = blockIdx.x * 128;
  const int tid = threadIdx.x;

  for (int i = tid; i < H4; i += 256) asv[i] = g_Amat[(size_t)s * H4 + i];
  if (tid < AH) {
    xcw[tid] = g_Xc0[s * AH + tid];
    w2s[tid] = a0W2[tid];
  }

  const int sdd = tid >> 1;
  const int skh = (tid & 1) * 8;
  const int scol = sdd + ((sdd >> 3) << 2);
  const float* bsrc = &g_Bmat[(size_t)(d0 + sdd) * H4];

  const int dt = (tid & 15) * 8;
  const int acol = dt + ((dt >> 3) << 2);
  const int ct = (tid >> 4) * 8;
  unsigned long long acc[4][8] = {};

  {
    float4 b0 = *(const float4*)&bsrc[skh];
    float4 b1 = *(const float4*)&bsrc[skh + 4];
    const float4* msrc = (const float4*)&g_M[0];
    float4 mr0 = msrc[tid];
    float4 mr1 = msrc[256 + tid];
    const float* av = &asv[skh];
    Ts[0][skh + 0][scol] = fmaxf(av[0] + b0.x, 0.f);
    Ts[0][skh + 1][scol] = fmaxf(av[1] + b0.y, 0.f);
    Ts[0][skh + 2][scol] = fmaxf(av[2] + b0.z, 0.f);
    Ts[0][skh + 3][scol] = fmaxf(av[3] + b0.w, 0.f);
    Ts[0][skh + 4][scol] = fmaxf(av[4] + b1.x, 0.f);
    Ts[0][skh + 5][scol] = fmaxf(av[5] + b1.y, 0.f);
    Ts[0][skh + 6][scol] = fmaxf(av[6] + b1.z, 0.f);
    Ts[0][skh + 7][scol] = fmaxf(av[7] + b1.w, 0.f);
    ((float4*)&Msm[0][0][0])[tid] = mr0;
    ((float4*)&Msm[0][0][0])[256 + tid] = mr1;
  }
  __syncthreads();

  for (int tile = 0; tile < 64; tile++) {
    const int cur = tile & 1;
    float4 b0, b1, mr0, mr1;
    if (tile < 63) {
      const int kn = (tile + 1) * 16;
      b0 = *(const float4*)&bsrc[kn + skh];
      b1 = *(const float4*)&bsrc[kn + skh + 4];
      const float4* msrc = (const float4*)&g_M[(size_t)kn * ED];
      mr0 = msrc[tid];
      mr1 = msrc[256 + tid];
    }
#pragma unroll
    for (int k = 0; k < 16; k++) {
      ulonglong2 aA = *(const ulonglong2*)&Ts[cur][k][acol];
      ulonglong2 aB = *(const ulonglong2*)&Ts[cur][k][acol + 4];
      float4 m0 = *(const float4*)&Msm[cur][k][ct];
      float4 m1 = *(const float4*)&Msm[cur][k][ct + 4];
      const float mv[8] = {m0.x, m0.y, m0.z, m0.w, m1.x, m1.y, m1.z, m1.w};
#pragma unroll
      for (int c = 0; c < 8; c++) {
        const unsigned long long mm = dup2(mv[c]);
        ffma2(acc[0][c], aA.x, mm);
        ffma2(acc[1][c], aA.y, mm);
        ffma2(acc[2][c], aB.x, mm);
        ffma2(acc[3][c], aB.y, mm);
      }
    }
    if (tile < 63) {
      const int nb = cur ^ 1;
      const float* av = &asv[(tile + 1) * 16 + skh];
      Ts[nb][skh + 0][scol] = fmaxf(av[0] + b0.x, 0.f);
      Ts[nb][skh + 1][scol] = fmaxf(av[1] + b0.y, 0.f);
      Ts[nb][skh + 2][scol] = fmaxf(av[2] + b0.z, 0.f);
      Ts[nb][skh + 3][scol] = fmaxf(av[3] + b0.w, 0.f);
      Ts[nb][skh + 4][scol] = fmaxf(av[4] + b1.x, 0.f);
      Ts[nb][skh + 5][scol] = fmaxf(av[5] + b1.y, 0.f);
      Ts[nb][skh + 6][scol] = fmaxf(av[6] + b1.z, 0.f);
      Ts[nb][skh + 7][scol] = fmaxf(av[7] + b1.w, 0.f);
      ((float4*)&Msm[nb][0][0])[tid] = mr0;
      ((float4*)&Msm[nb][0][0])[256 + tid] = mr1;
    }
    __syncthreads();
  }

  const int ctg = tid >> 4;
  if (ct < AH) {
#pragma unroll
    for (int p = 0; p < 4; p++) {
      float se = 0.f, so = 0.f;
#pragma unroll
      for (int c = 0; c < 8; c++) {
        float2 v = up2(acc[p][c]);
        se += fmaxf(v.x + xcw[ct + c], 0.f) * w2s[ct + c];
        so += fmaxf(v.y + xcw[ct + c], 0.f) * w2s[ct + c];
      }
      patt[dt + 2 * p][ctg] = se;
      patt[dt + 2 * p + 1][ctg] = so;
    }
  } else {
    const int chb = ct - AH;
#pragma unroll
    for (int p = 0; p < 4; p++) {
      float2 v0 = up2(acc[p][0]), v1 = up2(acc[p][1]);
      float2 v2 = up2(acc[p][2]), v3 = up2(acc[p][3]);
      float2 v4 = up2(acc[p][4]), v5 = up2(acc[p][5]);
      float2 v6 = up2(acc[p][6]), v7 = up2(acc[p][7]);
      const size_t base = ((size_t)s * N_NODES + d0 + dt + 2 * p) * AH + chb;
      *(float4*)&g_hid1[base] = make_float4(v0.x, v1.x, v2.x, v3.x);
      *(float4*)&g_hid1[base + 4] = make_float4(v4.x, v5.x, v6.x, v7.x);
      *(float4*)&g_hid1[base + AH] = make_float4(v0.y, v1.y, v2.y, v3.y);
      *(float4*)&g_hid1[base + AH + 4] = make_float4(v4.y, v5.y, v6.y, v7.y);
    }
  }
  __syncthreads();
  if (tid < 128) {
    float v = 0.f;
#pragma unroll
    for (int g = 0; g < 8; g++) v += patt[tid][g];
    float att = (d0 + tid == s) ? 0.f : fast_sigmoid(v + a0b2[0]);
    g_Att0T[(size_t)(d0 + tid) * N_NODES + s] = att;
  }
}

// ------------------ attention layer 1 row-sums w[s] -------------------------
__global__ void att1w_kernel(const float* __restrict__ a1W1,
                             const float* __restrict__ a1W2,
                             const float* __restrict__ a1b2) {
  const int s = blockIdx.x;
  const int warp = threadIdx.x >> 5, lane = threadIdx.x & 31;
  __shared__ float pxc[AH][5];
  __shared__ float xc[AH], w2[AH];
  __shared__ float wsum[8];
  {
    const int i = threadIdx.x >> 2, q = threadIdx.x & 3;
    const float* xs = &g_x1[s * H + q * 64];
    const float* wcol = &a1W1[(size_t)(ED + q * 64) * AH + i];
    float acc = 0.f;
#pragma unroll 8
    for (int k = 0; k < 64; k++) acc += xs[k] * wcol[k * AH];
    pxc[i][q] = acc;
  }
  __syncthreads();
  if (threadIdx.x < AH) {
    xc[threadIdx.x] = pxc[threadIdx.x][0] + pxc[threadIdx.x][1] +
                      pxc[threadIdx.x][2] + pxc[threadIdx.x][3] +
                      g_cb1[threadIdx.x];
    w2[threadIdx.x] = a1W2[threadIdx.x];
  }
  __syncthreads();
  const float b2 = a1b2[0];
  float accv = 0.f;
  for (int d = warp; d < N_NODES; d += 8) {
    float2 h2 = *(const float2*)&g_hid1[(((size_t)s) * N_NODES + d) * AH + lane * 2];
    float v = fmaxf(h2.x + xc[lane * 2], 0.f) * w2[lane * 2] +
              fmaxf(h2.y + xc[lane * 2 + 1], 0.f) * w2[lane * 2 + 1];
    for (int o = 16; o > 0; o >>= 1) v += __shfl_down_sync(0xffffffffu, v, o);
    if (lane == 0 && d != s) accv += fast_sigmoid(v + b2);
  }
  if (lane == 0) wsum[warp] = accv;
  __syncthreads();
  if (threadIdx.x == 0) {
    float t = 0.f;
    for (int i = 0; i < 8; i++) t += wsum[i];
    g_w[s] = t;
  }
}

// --------------------------- final reduction --------------------------------
__global__ void final_kernel(const float* __restrict__ c1W,
                             const float* __restrict__ c1b,
                             float* __restrict__ out) {
  __shared__ float v[H];
  __shared__ float wsh[N_NODES];
  const int tid = threadIdx.x;  // 256
  for (int i = tid; i < N_NODES; i += blockDim.x) wsh[i] = g_w[i];
  __syncthreads();
  float s = 0.f;
  for (int n = 0; n < N_NODES; n++) s += wsh[n] * g_x1[n * H + tid];
  v[tid] = s;
  __syncthreads();
  float o = (float)N_NODES * c1b[tid];
  for (int h = 0; h < H; h++) o += v[h] * c1W[h * H + tid];
  out[tid] = o;
}

// ------------------------------- launcher -----------------------------------
static float* sym_addr(const void* symbol) {
  void* p = nullptr;
  cudaGetSymbolAddress(&p, symbol);
  return (float*)p;
}

extern "C" void kernel_launch(void* const* d_in, const int* in_sizes, int n_in,
                              void* d_out, int out_size) {
  const float* z = (const float*)d_in[0];
  const float* Wih = (const float*)d_in[1];
  const float* Whh = (const float*)d_in[2];
  const float* bih = (const float*)d_in[3];
  const float* bhh = (const float*)d_in[4];
  const float* egW1 = (const float*)d_in[5];
  const float* egb1 = (const float*)d_in[6];
  const float* egW2 = (const float*)d_in[7];
  const float* egb2 = (const float*)d_in[8];
  const float* a0W1 = (const float*)d_in[9];
  const float* a0b1 = (const float*)d_in[10];
  const float* a0W2 = (const float*)d_in[11];
  const float* a0b2 = (const float*)d_in[12];
  const float* a1W1 = (const float*)d_in[13];
  const float* a1b1 = (const float*)d_in[14];
  const float* a1W2 = (const float*)d_in[15];
  const float* a1b2 = (const float*)d_in[16];
  const float* c0W = (const float*)d_in[17];
  const float* c0b = (const float*)d_in[18];
  const float* c1W = (const float*)d_in[19];
  const float* c1b = (const float*)d_in[20];
  float* out = (float*)d_out;

  // 0: setup — M halves (z=0,1) + cb0/cb1 (z=2)
  setup_kernel<<<dim3(1, H4 / 64, 3), 256>>>(egW2, a0W1, a1W1, egb2, a0b1,
                                             a1b1);

  // 1: GRU -> nodes
  gru_kernel<<<GRU_CTAS, 384>>>(z, Wih, Whh, bih, bhh);

  // 2: A/B/Xc0 (z=0: Amat, z=1: Bmat, z=2: Xc0)
  abxc_kernel<<<dim3(H4 / 64, N_NODES / 64, 3), 256>>>(
      sym_addr(g_nodes), egW1, egb1, a0W1 + (size_t)ED * AH);

  // 3 (PROFILED): edge GEMM + fused att0
  edge_kernel<<<dim3(N_NODES / 128, N_NODES), 256>>>(a0W2, a0b2);

  // 4: x1 = relu((Att0T @ nodes) @ c0W + c0b)  — fused, agg never in global
  fusedconv_kernel<<<dim3(1, N_NODES / 16), 256>>>(c0W, c0b);

  // 5: w[s] = sum_d att1(s,d)
  att1w_kernel<<<N_NODES, 256>>>(a1W1, a1W2, a1b2);

  // 6: out = (sum_s w[s] x1[s]) @ c1W + 384*c1b
  final_kernel<<<1, H>>>(c1W, c1b, out);
}